// round 11
// baseline (speedup 1.0000x reference)
#include <cuda_runtime.h>
#include <math_constants.h>
#include <cstdint>

typedef unsigned long long ULL;

#define Bc 1024
#define Sc 2048
#define Hc 50
#define TT 128
#define NTILE 16
#define NTH 256
#define RS 60
#define L2E 1.4426950408889634f

// ---- dynamic SMEM layout (bytes) ----
#define OFF_BUF0  0                // float[128*60]  30720
#define OFF_BUF1  30720            // float[128*60]  30720 (transient bfrag at setup)
#define OFF_WS    61440            // float[64]
#define OFF_PPV   61696            // float[64]
#define OFF_SPART 61952            // float[4][2][32]  1024
#define OFF_SL    63488            // float[8]
#define OFF_SCTX  63552            // ULL[8][25]
#define SMEM_BYTES (63552 + 1600)

__device__ __forceinline__ uint32_t smem_u32(const void* p) {
    uint32_t a;
    asm("{ .reg .u64 t; cvta.to.shared.u64 t, %1; cvt.u32.u64 %0, t; }" : "=r"(a) : "l"(p));
    return a;
}
__device__ __forceinline__ float fast_ex2(float x) {
    float r; asm("ex2.approx.f32 %0, %1;" : "=f"(r) : "f"(x)); return r;
}
__device__ __forceinline__ float fast_tanh(float x) {
    float r; asm("tanh.approx.f32 %0, %1;" : "=f"(r) : "f"(x)); return r;
}
__device__ __forceinline__ ULL pack2(float lo, float hi) {
    ULL r; asm("mov.b64 %0, {%1, %2};" : "=l"(r) : "f"(lo), "f"(hi)); return r;
}
__device__ __forceinline__ void unpack2(ULL v, float& lo, float& hi) {
    asm("mov.b64 {%0, %1}, %2;" : "=f"(lo), "=f"(hi) : "l"(v));
}
#define FMA2(d, a, b) asm("fma.rn.f32x2 %0, %1, %2, %0;" : "+l"(d) : "l"(a), "l"(b))
__device__ __forceinline__ uint32_t to_tf32(float v) {
    uint32_t u; asm("cvt.rna.tf32.f32 %0, %1;" : "=r"(u) : "f"(v)); return u;
}

#define MMA_TF32(C, A, B0, B1)                                                  \
    asm("mma.sync.aligned.m16n8k8.row.col.f32.tf32.tf32.f32 "                   \
        "{%0,%1,%2,%3}, {%4,%5,%6,%7}, {%8,%9}, {%0,%1,%2,%3};"                 \
        : "+f"((C)[0]), "+f"((C)[1]), "+f"((C)[2]), "+f"((C)[3])                \
        : "r"((A)[0]), "r"((A)[1]), "r"((A)[2]), "r"((A)[3]), "r"(B0), "r"(B1))

#define CP_ASYNC8(dst, src) \
    asm volatile("cp.async.ca.shared.global [%0], [%1], 8;" :: "r"(dst), "l"(src))
#define CP_COMMIT() asm volatile("cp.async.commit_group;" ::: "memory")
#define CP_WAIT1()  asm volatile("cp.async.wait_group 1;" ::: "memory")
#define PAIR_BAR(id) asm volatile("bar.sync %0, 64;" :: "r"(id) : "memory")

__global__ __launch_bounds__(NTH, 2)
void additive_attn_kernel(const float* __restrict__ dec,
                          const float* __restrict__ enc,     // (S,B,H)
                          const int*   __restrict__ mask,    // (B,S)
                          const float* __restrict__ Wp,
                          const float* __restrict__ We,
                          const float* __restrict__ Ws,
                          float* __restrict__ out)
{
    extern __shared__ __align__(16) char smem[];
    const uint32_t smb = smem_u32(smem);
    float* ws    = (float*)(smem + OFF_WS);
    float* ppv   = (float*)(smem + OFF_PPV);
    float* spart = (float*)(smem + OFF_SPART);   // [wr][wc][32]
    float* sl    = (float*)(smem + OFF_SL);
    ULL (*sctx)[25] = (ULL(*)[25])(smem + OFF_SCTX);

    const int b    = blockIdx.x;
    const int tid  = threadIdx.x;
    const int lane = tid & 31;
    const int wid  = tid >> 5;
    const int g    = lane >> 2;
    const int c    = lane & 3;
    const int wr   = wid & 3;      // pair id / token block (32 tokens)
    const int wc   = wid >> 2;     // n half
    const int barid = wr + 1;      // named barrier for this pair
    const int pairbase = wr * 32;  // first token row of this pair

    // ---- setup: pp, ws ----
    if (tid < 64) {
        float pp = 0.0f;
        if (tid < Hc) {
            #pragma unroll
            for (int k = 0; k < Hc; k++)
                pp = fmaf(Wp[tid * Hc + k], dec[b * Hc + k], pp);
        }
        ppv[tid] = pp;
        ws[tid]  = (tid < Hc) ? Ws[tid] : 0.0f;
    }
    __syncthreads();

    // ---- build B fragments (fragment-major, tf32) in transient buf1 region ----
    uint32_t* bfrag = (uint32_t*)(smem + OFF_BUF1);
    for (int i = tid; i < 7 * 8 * 32 * 2; i += NTH) {
        int r  = i & 1;
        int ln = (i >> 1) & 31;
        int nb = (i >> 6) & 7;
        int s  = i >> 9;
        int k  = 8 * s + (ln & 3) + 4 * r;
        int n  = nb * 8 + (ln >> 2);
        float v = 0.0f;
        if (n < Hc) {
            if (k < Hc)       v = We[n * Hc + k];
            else if (k == 50) v = ppv[n];
        }
        bfrag[i] = to_tf32(v);
    }
    __syncthreads();

    // ---- hoist B frags + ws to registers ----
    uint2 Breg[7][4];
    #pragma unroll
    for (int s = 0; s < 7; s++)
        #pragma unroll
        for (int nb = 0; nb < 4; nb++)
            Breg[s][nb] = *reinterpret_cast<const uint2*>(
                bfrag + s * 512 + (wc * 4 + nb) * 64 + lane * 2);
    float wsr[4][2];
    #pragma unroll
    for (int nb = 0; nb < 4; nb++) {
        wsr[nb][0] = ws[wc * 32 + nb * 8 + 2 * c];
        wsr[nb][1] = ws[wc * 32 + nb * 8 + 2 * c + 1];
    }
    __syncthreads();   // done reading bfrag; buf1 free

    // ---- init pad cols 50..59 in BOTH buffers ----
    for (int i = tid; i < TT * 10; i += NTH) {
        int t = i / 10, cc = i - 10 * (i / 10);
        float v = (cc == 0) ? 1.0f : 0.0f;          // col 50 = 1.0 (pp lane)
        ((float*)(smem + OFF_BUF0))[t * RS + 50 + cc] = v;
        ((float*)(smem + OFF_BUF1))[t * RS + 50 + cc] = v;
    }
    __syncthreads();   // pads visible to everyone before pair-local loop

    // ---- staging geometry: warp stages its own 16 context rows ----
    // rows: myrow0 = pairbase + wc*16 + i, i in 0..15; lane = 8B chunk (0..24)
    const int myrow0 = pairbase + wc * 16;
    const float* encb = enc + (size_t)b * Hc;
    const bool st_on = (lane < 25);
    const size_t tok_stride = (size_t)(Bc * Hc);
    const uint32_t d_off = (uint32_t)(myrow0 * RS + 2 * lane) * 4u;
    const size_t  s_off = (size_t)myrow0 * tok_stride + 2 * lane;

    // ---- prologue: prefetch own rows of tile 0 into buf0 ----
    if (st_on) {
        const float* s0 = encb + s_off;
        uint32_t d0 = smb + OFF_BUF0 + d_off;
        #pragma unroll
        for (int i = 0; i < 16; i++)
            CP_ASYNC8(d0 + i * (RS * 4), s0 + (size_t)i * tok_stride);
    }
    CP_COMMIT();

    float lw = 0.0f;
    ULL ctx2 = 0ull;
    const bool skip_nb3 = (wc == 1);   // n 56..63 all have ws == 0

    #pragma unroll 1
    for (int tt = 0; tt < NTILE; tt++) {
        const int par = tt & 1;
        PAIR_BAR(barid);   // pair's reads of buf[par^1] (iter tt-1) done

        int mkv = 1;
        if (lane < 16)
            mkv = mask[(size_t)b * Sc + tt * TT + myrow0 + lane];

        // ---- prefetch own rows of tile tt+1 into the other buffer ----
        if (tt + 1 < NTILE && st_on) {
            const float* sn = encb + (size_t)(tt + 1) * TT * tok_stride + s_off;
            uint32_t dn = smb + (par ? OFF_BUF0 : OFF_BUF1) + d_off;
            #pragma unroll
            for (int i = 0; i < 16; i++)
                CP_ASYNC8(dn + i * (RS * 4), sn + (size_t)i * tok_stride);
        }
        CP_COMMIT();
        CP_WAIT1();        // own cp.async for tile tt done
        PAIR_BAR(barid);   // partner's tile-tt rows visible too

        const float* buf = (const float*)(smem + (par ? OFF_BUF1 : OFF_BUF0));
        const float* pA0 = buf + (pairbase + g) * RS + c;

        // ---- GEMM: warp = 32 tokens x 32 n ----
        float C[2][4][4];
        #pragma unroll
        for (int mt = 0; mt < 2; mt++)
            #pragma unroll
            for (int nb = 0; nb < 4; nb++)
                #pragma unroll
                for (int q = 0; q < 4; q++) C[mt][nb][q] = 0.0f;

        #pragma unroll
        for (int s = 0; s < 7; s++) {
            uint32_t A[2][4];
            #pragma unroll
            for (int mt = 0; mt < 2; mt++) {
                const float* p = pA0 + mt * (16 * RS) + 8 * s;
                A[mt][0] = __float_as_uint(p[0]);
                A[mt][1] = __float_as_uint(p[8 * RS]);
                A[mt][2] = __float_as_uint(p[4]);
                A[mt][3] = __float_as_uint(p[8 * RS + 4]);
            }
            #pragma unroll
            for (int nb = 0; nb < 4; nb++) {
                if (nb == 3 && skip_nb3) continue;
                MMA_TF32(C[0][nb], A[0], Breg[s][nb].x, Breg[s][nb].y);
                MMA_TF32(C[1][nb], A[1], Breg[s][nb].x, Breg[s][nb].y);
            }
        }

        // ---- epilogue: part = sum_n ws[n] * tanh(D) ----
        float part[4] = {0.0f, 0.0f, 0.0f, 0.0f};
        #pragma unroll
        for (int mt = 0; mt < 2; mt++)
            #pragma unroll
            for (int nb = 0; nb < 4; nb++) {
                if (nb == 3 && skip_nb3) continue;
                #pragma unroll
                for (int hi = 0; hi < 2; hi++) {
                    part[mt*2+hi] = fmaf(wsr[nb][0], fast_tanh(C[mt][nb][hi*2]),   part[mt*2+hi]);
                    part[mt*2+hi] = fmaf(wsr[nb][1], fast_tanh(C[mt][nb][hi*2+1]), part[mt*2+hi]);
                }
            }
        #pragma unroll
        for (int q = 0; q < 4; q++) {
            part[q] += __shfl_xor_sync(0xffffffffu, part[q], 1);
            part[q] += __shfl_xor_sync(0xffffffffu, part[q], 2);
        }
        if (c == 0) {
            #pragma unroll
            for (int mt = 0; mt < 2; mt++)
                #pragma unroll
                for (int hi = 0; hi < 2; hi++)
                    spart[(wr * 2 + wc) * 32 + mt * 16 + hi * 8 + g] = part[mt*2+hi];
        }
        PAIR_BAR(barid);   // pair partials visible

        // ---- exp in-lane (lane<16 holds token myrow0+lane), then context ----
        float pv = 0.0f;
        if (lane < 16) {
            int tl = wc * 16 + lane;   // token within pair block
            float sc = spart[wr * 64 + tl] + spart[wr * 64 + 32 + tl];
            pv = mkv ? fast_ex2(sc * L2E) : 0.0f;
        }
        const float* crow = buf + myrow0 * RS + 2 * lane;
        #pragma unroll 4
        for (int r = 0; r < 16; r++) {
            float p = __shfl_sync(0xffffffffu, pv, r);
            lw += p;
            if (lane < 25) {
                ULL e2 = *reinterpret_cast<const ULL*>(crow + r * RS);
                FMA2(ctx2, pack2(p, p), e2);
            }
        }
    }

    // ---- finalize ----
    if (lane == 0) sl[wid] = lw;
    if (lane < 25) sctx[wid][lane] = ctx2;
    __syncthreads();
    if (tid < 25) {
        float sx = 0.0f, sy = 0.0f, lt = 0.0f;
        #pragma unroll
        for (int i = 0; i < 8; i++) {
            float x, y; unpack2(sctx[i][tid], x, y);
            sx += x; sy += y; lt += sl[i];
        }
        float inv = 1.0f / lt;
        float2 o; o.x = sx * inv; o.y = sy * inv;
        *reinterpret_cast<float2*>(out + (size_t)b * Hc + 2 * tid) = o;
    }
}

extern "C" void kernel_launch(void* const* d_in, const int* in_sizes, int n_in,
                              void* d_out, int out_size) {
    const float* dec  = (const float*)d_in[0];
    const float* enc  = (const float*)d_in[1];
    const int*   mask = (const int*)  d_in[2];
    const float* Wp   = (const float*)d_in[3];
    const float* We   = (const float*)d_in[4];
    const float* Ws   = (const float*)d_in[5];
    float* out = (float*)d_out;

    cudaFuncSetAttribute(additive_attn_kernel,
                         cudaFuncAttributeMaxDynamicSharedMemorySize, SMEM_BYTES);
    additive_attn_kernel<<<Bc, NTH, SMEM_BYTES>>>(dec, enc, mask, Wp, We, Ws, out);
}

// round 12
// speedup vs baseline: 1.1114x; 1.1114x over previous
#include <cuda_runtime.h>
#include <math_constants.h>
#include <cstdint>

typedef unsigned long long ULL;

#define Bc 1024
#define Sc 2048
#define Hc 50
#define TT 128
#define NTILE 16
#define NTH 256
#define RS 60
#define L2E 1.4426950408889634f

// ---- dynamic SMEM layout (bytes) ----
#define OFF_BUF0  0                // float[128*60]  30720
#define OFF_BUF1  30720            // float[128*60]  30720 (transient bfrag at setup)
#define OFF_WS    61440            // float[64]
#define OFF_PPV   61696            // float[64]
#define OFF_SPART 61952            // float[2*128]   1024
#define OFF_MBITS 62976            // uint32[64]      256
#define OFF_SL    63232            // float[8]         32
#define OFF_SCTX  63264            // ULL[8][25]     1600
#define SMEM_BYTES 64864

__device__ __forceinline__ uint32_t smem_u32(const void* p) {
    uint32_t a;
    asm("{ .reg .u64 t; cvta.to.shared.u64 t, %1; cvt.u32.u64 %0, t; }" : "=r"(a) : "l"(p));
    return a;
}
__device__ __forceinline__ float fast_ex2(float x) {
    float r; asm("ex2.approx.f32 %0, %1;" : "=f"(r) : "f"(x)); return r;
}
__device__ __forceinline__ float fast_tanh(float x) {
    float r; asm("tanh.approx.f32 %0, %1;" : "=f"(r) : "f"(x)); return r;
}
__device__ __forceinline__ ULL pack2(float lo, float hi) {
    ULL r; asm("mov.b64 %0, {%1, %2};" : "=l"(r) : "f"(lo), "f"(hi)); return r;
}
__device__ __forceinline__ void unpack2(ULL v, float& lo, float& hi) {
    asm("mov.b64 {%0, %1}, %2;" : "=f"(lo), "=f"(hi) : "l"(v));
}
#define FMA2(d, a, b) asm("fma.rn.f32x2 %0, %1, %2, %0;" : "+l"(d) : "l"(a), "l"(b))
__device__ __forceinline__ ULL add2(ULL a, ULL b) {
    ULL r; asm("add.rn.f32x2 %0, %1, %2;" : "=l"(r) : "l"(a), "l"(b)); return r;
}
__device__ __forceinline__ uint32_t to_tf32(float v) {
    uint32_t u; asm("cvt.rna.tf32.f32 %0, %1;" : "=r"(u) : "f"(v)); return u;
}

#define MMA_TF32(C, A, B0, B1)                                                  \
    asm("mma.sync.aligned.m16n8k8.row.col.f32.tf32.tf32.f32 "                   \
        "{%0,%1,%2,%3}, {%4,%5,%6,%7}, {%8,%9}, {%0,%1,%2,%3};"                 \
        : "+f"((C)[0]), "+f"((C)[1]), "+f"((C)[2]), "+f"((C)[3])                \
        : "r"((A)[0]), "r"((A)[1]), "r"((A)[2]), "r"((A)[3]), "r"(B0), "r"(B1))

#define CP_ASYNC8(dst, src) \
    asm volatile("cp.async.ca.shared.global [%0], [%1], 8;" :: "r"(dst), "l"(src))
#define CP_COMMIT() asm volatile("cp.async.commit_group;" ::: "memory")
#define CP_WAIT0()  asm volatile("cp.async.wait_group 0;" ::: "memory")

__global__ __launch_bounds__(NTH, 2)
void additive_attn_kernel(const float* __restrict__ dec,
                          const float* __restrict__ enc,     // (S,B,H)
                          const int*   __restrict__ mask,    // (B,S)
                          const float* __restrict__ Wp,
                          const float* __restrict__ We,
                          const float* __restrict__ Ws,
                          float* __restrict__ out)
{
    extern __shared__ __align__(16) char smem[];
    const uint32_t smb = smem_u32(smem);
    float*    ws    = (float*)(smem + OFF_WS);
    float*    ppv   = (float*)(smem + OFF_PPV);
    float*    spart = (float*)(smem + OFF_SPART);
    uint32_t* mbits = (uint32_t*)(smem + OFF_MBITS);
    float*    sl    = (float*)(smem + OFF_SL);
    ULL (*sctx)[25] = (ULL(*)[25])(smem + OFF_SCTX);

    const int b    = blockIdx.x;
    const int tid  = threadIdx.x;
    const int lane = tid & 31;
    const int wid  = tid >> 5;
    const int g    = lane >> 2;
    const int c    = lane & 3;
    const int wr   = wid & 3;      // token block (32 tokens)
    const int wc   = wid >> 2;     // n half

    // ---- setup: pp, ws ----
    if (tid < 64) {
        float pp = 0.0f;
        if (tid < Hc) {
            #pragma unroll
            for (int k = 0; k < Hc; k++)
                pp = fmaf(Wp[tid * Hc + k], dec[b * Hc + k], pp);
        }
        ppv[tid] = pp;
        ws[tid]  = (tid < Hc) ? Ws[tid] : 0.0f;
    }
    // ---- pack mask row into bitmask (2048 bits = 64 u32) ----
    #pragma unroll
    for (int chunk = 0; chunk < 8; chunk++) {
        int m = mask[(size_t)b * Sc + chunk * 256 + tid];
        unsigned bal = __ballot_sync(0xffffffffu, m != 0);
        if (lane == 0) mbits[chunk * 8 + wid] = bal;
    }
    __syncthreads();

    // ---- build B fragments (fragment-major, tf32) in transient buf1 region ----
    uint32_t* bfrag = (uint32_t*)(smem + OFF_BUF1);
    for (int i = tid; i < 7 * 8 * 32 * 2; i += NTH) {
        int r  = i & 1;
        int ln = (i >> 1) & 31;
        int nb = (i >> 6) & 7;
        int s  = i >> 9;
        int k  = 8 * s + (ln & 3) + 4 * r;
        int n  = nb * 8 + (ln >> 2);
        float v = 0.0f;
        if (n < Hc) {
            if (k < Hc)       v = We[n * Hc + k];
            else if (k == 50) v = ppv[n];
        }
        bfrag[i] = to_tf32(v);
    }
    __syncthreads();

    // ---- hoist B frags + ws to registers ----
    uint2 Breg[7][4];
    #pragma unroll
    for (int s = 0; s < 7; s++)
        #pragma unroll
        for (int nb = 0; nb < 4; nb++)
            Breg[s][nb] = *reinterpret_cast<const uint2*>(
                bfrag + s * 512 + (wc * 4 + nb) * 64 + lane * 2);
    float wsr[4][2];
    #pragma unroll
    for (int nb = 0; nb < 4; nb++) {
        wsr[nb][0] = ws[wc * 32 + nb * 8 + 2 * c];
        wsr[nb][1] = ws[wc * 32 + nb * 8 + 2 * c + 1];
    }
    __syncthreads();   // done reading bfrag; buf1 free

    // ---- init pad cols 50..59 in BOTH buffers ----
    for (int i = tid; i < TT * 10; i += NTH) {
        int t = i / 10, cc = i - 10 * (i / 10);
        float v = (cc == 0) ? 1.0f : 0.0f;          // col 50 = 1.0 (pp lane)
        ((float*)(smem + OFF_BUF0))[t * RS + 50 + cc] = v;
        ((float*)(smem + OFF_BUF1))[t * RS + 50 + cc] = v;
    }

    // ---- staging geometry: lane = 8B chunk (0..24), token = wid + 8i ----
    const float* encb = enc + (size_t)b * Hc;
    const bool st_on = (lane < 25);
    const size_t tok_stride = (size_t)(Bc * Hc);
    const uint32_t d_off = (uint32_t)(wid * RS + 2 * lane) * 4u;
    const size_t  s_off = (size_t)wid * tok_stride + 2 * lane;

    // ---- prologue: prefetch tile 0 into buf0 ----
    if (st_on) {
        const float* s0 = encb + s_off;
        uint32_t d0 = smb + OFF_BUF0 + d_off;
        #pragma unroll
        for (int i = 0; i < 16; i++)
            CP_ASYNC8(d0 + i * (8 * RS * 4), s0 + (size_t)i * 8 * tok_stride);
    }
    CP_COMMIT();

    float lwA = 0.0f, lwB = 0.0f;
    ULL ctxA = 0ull, ctxB = 0ull;
    const bool skip_nb3 = (wc == 1);   // n 56..63 all have ws == 0
    const int  mshift   = (wid & 1) << 4;

    #pragma unroll 1
    for (int tt = 0; tt < NTILE; tt++) {
        const int par = tt & 1;

        CP_WAIT0();        // own prefetch of tile tt landed
        __syncthreads();   // => ALL warps' tile-tt rows visible,
                           //    AND all context(tt-1) reads of buf[par^1] done

        // ---- prefetch tile tt+1 into the other buffer (overlaps MMA below) ----
        if (tt + 1 < NTILE && st_on) {
            const float* sn = encb + (size_t)(tt + 1) * TT * tok_stride + s_off;
            uint32_t dn = smb + (par ? OFF_BUF0 : OFF_BUF1) + d_off;
            #pragma unroll
            for (int i = 0; i < 16; i++)
                CP_ASYNC8(dn + i * (8 * RS * 4), sn + (size_t)i * 8 * tok_stride);
        }
        CP_COMMIT();

        // mask bits for this warp's 16 context tokens (1 LDS broadcast)
        const uint32_t mw = mbits[tt * 4 + (wid >> 1)];

        const float* buf = (const float*)(smem + (par ? OFF_BUF1 : OFF_BUF0));
        const float* pA0 = buf + (wr * 32 + g) * RS + c;

        // ---- GEMM: warp = 32 tokens x 32 n ----
        float C[2][4][4];
        #pragma unroll
        for (int mt = 0; mt < 2; mt++)
            #pragma unroll
            for (int nb = 0; nb < 4; nb++)
                #pragma unroll
                for (int q = 0; q < 4; q++) C[mt][nb][q] = 0.0f;

        #pragma unroll
        for (int s = 0; s < 7; s++) {
            uint32_t A[2][4];
            #pragma unroll
            for (int mt = 0; mt < 2; mt++) {
                const float* p = pA0 + mt * (16 * RS) + 8 * s;
                A[mt][0] = __float_as_uint(p[0]);
                A[mt][1] = __float_as_uint(p[8 * RS]);
                A[mt][2] = __float_as_uint(p[4]);
                A[mt][3] = __float_as_uint(p[8 * RS + 4]);
            }
            #pragma unroll
            for (int nb = 0; nb < 4; nb++) {
                if (nb == 3 && skip_nb3) continue;
                MMA_TF32(C[0][nb], A[0], Breg[s][nb].x, Breg[s][nb].y);
                MMA_TF32(C[1][nb], A[1], Breg[s][nb].x, Breg[s][nb].y);
            }
        }

        // ---- epilogue: part = sum_n ws[n] * tanh(D) ----
        float part[4] = {0.0f, 0.0f, 0.0f, 0.0f};
        #pragma unroll
        for (int mt = 0; mt < 2; mt++)
            #pragma unroll
            for (int nb = 0; nb < 4; nb++) {
                if (nb == 3 && skip_nb3) continue;
                #pragma unroll
                for (int hi = 0; hi < 2; hi++) {
                    part[mt*2+hi] = fmaf(wsr[nb][0], fast_tanh(C[mt][nb][hi*2]),   part[mt*2+hi]);
                    part[mt*2+hi] = fmaf(wsr[nb][1], fast_tanh(C[mt][nb][hi*2+1]), part[mt*2+hi]);
                }
            }
        #pragma unroll
        for (int q = 0; q < 4; q++) {
            part[q] += __shfl_xor_sync(0xffffffffu, part[q], 1);
            part[q] += __shfl_xor_sync(0xffffffffu, part[q], 2);
        }
        if (c == 0) {
            #pragma unroll
            for (int mt = 0; mt < 2; mt++)
                #pragma unroll
                for (int hi = 0; hi < 2; hi++)
                    spart[wc * TT + wr * 32 + mt * 16 + hi * 8 + g] = part[mt*2+hi];
        }
        __syncthreads();   // pair partials visible

        // ---- exp in-lane (lane<16 holds token wid*16+lane), then context ----
        float pv = 0.0f;
        if (lane < 16) {
            int t = (wid << 4) + lane;
            float sc = spart[t] + spart[TT + t];
            int mk = (mw >> (mshift + lane)) & 1;
            pv = mk ? fast_ex2(sc * L2E) : 0.0f;
        }
        const float* crow = buf + (wid << 4) * RS + 2 * lane;
        #pragma unroll 2
        for (int r = 0; r < 16; r += 2) {
            float p0 = __shfl_sync(0xffffffffu, pv, r);
            float p1 = __shfl_sync(0xffffffffu, pv, r + 1);
            lwA += p0;
            lwB += p1;
            if (lane < 25) {
                ULL e0 = *reinterpret_cast<const ULL*>(crow + r * RS);
                ULL e1 = *reinterpret_cast<const ULL*>(crow + (r + 1) * RS);
                FMA2(ctxA, pack2(p0, p0), e0);
                FMA2(ctxB, pack2(p1, p1), e1);
            }
        }
    }

    // ---- finalize ----
    ULL   ctx2 = add2(ctxA, ctxB);
    float lw   = lwA + lwB;
    if (lane == 0) sl[wid] = lw;
    if (lane < 25) sctx[wid][lane] = ctx2;
    __syncthreads();
    if (tid < 25) {
        float sx = 0.0f, sy = 0.0f, lt = 0.0f;
        #pragma unroll
        for (int i = 0; i < 8; i++) {
            float x, y; unpack2(sctx[i][tid], x, y);
            sx += x; sy += y; lt += sl[i];
        }
        float inv = 1.0f / lt;
        float2 o; o.x = sx * inv; o.y = sy * inv;
        *reinterpret_cast<float2*>(out + (size_t)b * Hc + 2 * tid) = o;
    }
}

extern "C" void kernel_launch(void* const* d_in, const int* in_sizes, int n_in,
                              void* d_out, int out_size) {
    const float* dec  = (const float*)d_in[0];
    const float* enc  = (const float*)d_in[1];
    const int*   mask = (const int*)  d_in[2];
    const float* Wp   = (const float*)d_in[3];
    const float* We   = (const float*)d_in[4];
    const float* Ws   = (const float*)d_in[5];
    float* out = (float*)d_out;

    cudaFuncSetAttribute(additive_attn_kernel,
                         cudaFuncAttributeMaxDynamicSharedMemorySize, SMEM_BYTES);
    additive_attn_kernel<<<Bc, NTH, SMEM_BYTES>>>(dec, enc, mask, Wp, We, Ws, out);
}